// round 5
// baseline (speedup 1.0000x reference)
#include <cuda_runtime.h>
#include <math.h>

#define NB 32
#define NT 128
#define NF 128
#define NG 512

// SMEM strides (floats) — float4/LDS.128 aligned, conflict-free column reads
#define XS_S  132   // Xs [128][132]
#define WDS_S 36    // Wds[128][36]
#define SS_S  33    // Ss [128][33]
#define AS_S  132   // As [32][132]
#define CS_S  132   // Cs [32][132]
#define WKS_S 388   // Wks[32][388]  (3 gates x 128 + pad)

#define OFF_XS  0
#define OFF_WDS (OFF_XS  + NT * XS_S)
#define OFF_SS  (OFF_WDS + NT * WDS_S)
#define OFF_AS  (OFF_SS  + NT * SS_S)
#define OFF_CS  (OFF_AS  + 32 * AS_S)
#define OFF_WKS (OFF_CS  + 32 * CS_S)
#define SMEM_FLOATS (OFF_WKS + 32 * WKS_S)
#define SMEM_BYTES  (SMEM_FLOATS * 4)   // 186368

#define NTHR 512

__device__ __forceinline__ float sigf(float x) { return 1.0f / (1.0f + __expf(-x)); }

__device__ __forceinline__ void fma2(unsigned long long& d,
                                     unsigned long long a, unsigned long long b) {
    asm("fma.rn.f32x2 %0, %1, %2, %0;" : "+l"(d) : "l"(a), "l"(b));
}
__device__ __forceinline__ unsigned long long bcast2(float x) {
    unsigned long long d; unsigned int xi = __float_as_uint(x);
    asm("mov.b64 %0, {%1, %1};" : "=l"(d) : "r"(xi));
    return d;
}
__device__ __forceinline__ float2 unpk(unsigned long long v) {
    float2 f; asm("mov.b64 {%0, %1}, %2;" : "=f"(f.x), "=f"(f.y) : "l"(v));
    return f;
}

// ---------------------------------------------------------------------------
// Fused: per CTA = (batch b, 32 output rows i0..i0+31), 512 threads
// ---------------------------------------------------------------------------
__global__ __launch_bounds__(NTHR, 1)
void fused_attn(const float* __restrict__ X, const float* __restrict__ Wd,
                const float* __restrict__ Wk, const float* __restrict__ bl,
                float* __restrict__ out)
{
    extern __shared__ float sm[];
    float* Xs  = sm + OFF_XS;
    float* Wds = sm + OFF_WDS;
    float* Ss  = sm + OFF_SS;
    float* As  = sm + OFF_AS;
    float* Cs  = sm + OFF_CS;
    float* Wks = sm + OFF_WKS;

    const int b   = blockIdx.y;
    const int i0  = blockIdx.x * 32;
    const int tid = threadIdx.x;

    const float* Xb = X + b * NT * NF;

    // ---- stage X_b (128x128) and Wd[:128, i0:i0+32] ----
    for (int idx = tid; idx < NT * 32; idx += NTHR) {
        int t = idx >> 5, fv = idx & 31;
        *(float4*)&Xs[t * XS_S + fv * 4] = *(const float4*)&Xb[t * NF + fv * 4];
    }
    for (int idx = tid; idx < NT * 8; idx += NTHR) {
        int k = idx >> 3, jv = idx & 7;
        *(float4*)&Wds[k * WDS_S + jv * 4] = *(const float4*)&Wd[k * NT + i0 + jv * 4];
    }
    __syncthreads();

    // ---- K1: logits S[t][jl], 2x4 micro-tile ----
    {
        const int tx = tid & 7;    // jl quad: 8*4 = 32
        const int ty = tid >> 3;   // 64 row-pairs: rows ty*2, ty*2+1
        unsigned long long acc[2][2] = {};
#pragma unroll 8
        for (int k0 = 0; k0 < NF; k0 += 4) {
            float4 xr[2];
#pragma unroll
            for (int a = 0; a < 2; a++) xr[a] = *(const float4*)&Xs[(ty * 2 + a) * XS_S + k0];
#pragma unroll
            for (int kk = 0; kk < 4; ++kk) {
                ulonglong2 wp = *(const ulonglong2*)&Wds[(k0 + kk) * WDS_S + tx * 4];
#pragma unroll
                for (int a = 0; a < 2; a++) {
                    unsigned long long xx = bcast2(((const float*)&xr[a])[kk]);
                    fma2(acc[a][0], xx, wp.x); fma2(acc[a][1], xx, wp.y);
                }
            }
        }
#pragma unroll
        for (int a = 0; a < 2; a++) {
            float2 v0 = unpk(acc[a][0]), v1 = unpk(acc[a][1]);
            float* row = &Ss[(ty * 2 + a) * SS_S + tx * 4];
            row[0] = v0.x; row[1] = v0.y; row[2] = v1.x; row[3] = v1.y;
        }
    }
    __syncthreads();

    // ---- softmax over t per column (16 warps, 2 columns each) ----
    {
        const int w = tid >> 5, lane = tid & 31;
#pragma unroll
        for (int c = 0; c < 2; ++c) {
            const int jl = w * 2 + c;
            float v[4];
#pragma unroll
            for (int r = 0; r < 4; r++) v[r] = Ss[(lane + 32 * r) * SS_S + jl];
            float m = fmaxf(fmaxf(v[0], v[1]), fmaxf(v[2], v[3]));
#pragma unroll
            for (int o = 16; o > 0; o >>= 1) m = fmaxf(m, __shfl_xor_sync(0xffffffffu, m, o));
            float s = 0.0f;
#pragma unroll
            for (int r = 0; r < 4; r++) { v[r] = __expf(v[r] - m); s += v[r]; }
#pragma unroll
            for (int o = 16; o > 0; o >>= 1) s += __shfl_xor_sync(0xffffffffu, s, o);
            const float inv = 1.0f / s;
#pragma unroll
            for (int r = 0; r < 4; r++) As[jl * AS_S + lane + 32 * r] = v[r] * inv;
        }
    }
    __syncthreads();

    // ---- K2: CTX rows, 2x4 micro-tile ----
    {
        const int tx = tid & 31;   // f quad: 32*4 = 128
        const int ty = tid >> 5;   // 16 row-pairs: i rows ty*2, ty*2+1
        unsigned long long acc[2][2] = {};
#pragma unroll 8
        for (int t0 = 0; t0 < NT; t0 += 4) {
            float4 ar[2];
#pragma unroll
            for (int a = 0; a < 2; a++) ar[a] = *(const float4*)&As[(ty * 2 + a) * AS_S + t0];
#pragma unroll
            for (int kk = 0; kk < 4; ++kk) {
                ulonglong2 xp = *(const ulonglong2*)&Xs[(t0 + kk) * XS_S + tx * 4];
#pragma unroll
                for (int a = 0; a < 2; a++) {
                    unsigned long long aa = bcast2(((const float*)&ar[a])[kk]);
                    fma2(acc[a][0], aa, xp.x); fma2(acc[a][1], aa, xp.y);
                }
            }
        }
#pragma unroll
        for (int a = 0; a < 2; a++) {
            ulonglong2 v; v.x = acc[a][0]; v.y = acc[a][1];
            *(ulonglong2*)&Cs[(ty * 2 + a) * CS_S + tx * 4] = v;
        }
    }
    __syncthreads();

    // ---- K3: 3 gates in one pass, Wk streamed in 32-row tiles ----
    {
        const int tx = tid & 31;   // u quad
        const int ty = tid >> 5;   // i row pair
        const int gofs[3] = {0, 256, 384};   // zi, zc, zo
        unsigned long long acc[2][6] = {};

        for (int k0 = 0; k0 < NF; k0 += 32) {
            if (k0) __syncthreads();
            for (int idx = tid; idx < 32 * 96; idx += NTHR) {
                int k = idx / 96, v = idx % 96;
                int g = v >> 5, uv = v & 31;
                *(float4*)&Wks[k * WKS_S + g * 128 + uv * 4] =
                    *(const float4*)&Wk[(k0 + k) * NG + gofs[g] + uv * 4];
            }
            __syncthreads();
#pragma unroll
            for (int k4 = 0; k4 < 32; k4 += 4) {
                float4 cr[2];
#pragma unroll
                for (int a = 0; a < 2; a++) cr[a] = *(const float4*)&Cs[(ty * 2 + a) * CS_S + k0 + k4];
#pragma unroll
                for (int kk = 0; kk < 4; ++kk) {
                    unsigned long long cc[2];
#pragma unroll
                    for (int a = 0; a < 2; a++) cc[a] = bcast2(((const float*)&cr[a])[kk]);
#pragma unroll
                    for (int g = 0; g < 3; ++g) {
                        ulonglong2 wp = *(const ulonglong2*)&Wks[(k4 + kk) * WKS_S + g * 128 + tx * 4];
#pragma unroll
                        for (int a = 0; a < 2; a++) {
                            fma2(acc[a][2 * g],     cc[a], wp.x);
                            fma2(acc[a][2 * g + 1], cc[a], wp.y);
                        }
                    }
                }
            }
        }

        float blv[3][4];
#pragma unroll
        for (int g = 0; g < 3; ++g)
#pragma unroll
            for (int c = 0; c < 4; c++) blv[g][c] = __ldg(&bl[gofs[g] + tx * 4 + c]);

#pragma unroll
        for (int a = 0; a < 2; a++) {
            float z[3][4];
#pragma unroll
            for (int g = 0; g < 3; ++g) {
                float2 v0 = unpk(acc[a][2 * g]), v1 = unpk(acc[a][2 * g + 1]);
                z[g][0] = v0.x + blv[g][0]; z[g][1] = v0.y + blv[g][1];
                z[g][2] = v1.x + blv[g][2]; z[g][3] = v1.y + blv[g][3];
            }
            float h[4];
#pragma unroll
            for (int c = 0; c < 4; c++) {
                float cell = sigf(z[0][c]) * tanhf(z[1][c]);
                h[c] = sigf(z[2][c]) * tanhf(cell);
            }
            float4 v = make_float4(h[0], h[1], h[2], h[3]);
            *(float4*)&out[(b * NT + i0 + ty * 2 + a) * NF + tx * 4] = v;
        }
    }
}

extern "C" void kernel_launch(void* const* d_in, const int* in_sizes, int n_in,
                              void* d_out, int out_size)
{
    const float* X  = (const float*)d_in[0];   // (32,128,128)
    const float* Wd = (const float*)d_in[1];   // (256,128) -- rows [0:128)
    const float* Wk = (const float*)d_in[3];   // (128,512)
    const float* bl = (const float*)d_in[5];   // (512,)
    float* out = (float*)d_out;                // (32,128,128)

    cudaFuncSetAttribute(fused_attn, cudaFuncAttributeMaxDynamicSharedMemorySize, SMEM_BYTES);
    fused_attn<<<dim3(4, NB), NTHR, SMEM_BYTES>>>(X, Wd, Wk, bl, out);
}

// round 7
// speedup vs baseline: 1.4487x; 1.4487x over previous
#include <cuda_runtime.h>
#include <math.h>

#define NB 32
#define NT 128
#define NF 128
#define NG 512

#define ITILE 16
#define NTHR  256

// SMEM strides/offsets (floats)
#define XS_S  132
#define WDS_S 16
#define AS_S  132
#define CS_S  132
#define WKS_S 384

#define OFF_XS  0
#define OFF_WDS (OFF_XS  + NT * XS_S)        // 16896
#define OFF_AS  (OFF_WDS + NT * WDS_S)       // 18944
#define OFF_CS  (OFF_AS  + ITILE * AS_S)     // 21056
#define OFF_WKS (OFF_CS  + ITILE * CS_S)     // 23168
#define SMEM_FLOATS (OFF_WKS + 8 * WKS_S)    // 26240
#define SMEM_BYTES  (SMEM_FLOATS * 4)        // 104960 -> 2 CTAs/SM

__device__ __forceinline__ float sigf(float x) { return 1.0f / (1.0f + __expf(-x)); }

__device__ __forceinline__ void fma2(unsigned long long& d,
                                     unsigned long long a, unsigned long long b) {
    asm("fma.rn.f32x2 %0, %1, %2, %0;" : "+l"(d) : "l"(a), "l"(b));
}
__device__ __forceinline__ unsigned long long bcast2(float x) {
    unsigned long long d; unsigned int xi = __float_as_uint(x);
    asm("mov.b64 %0, {%1, %1};" : "=l"(d) : "r"(xi));
    return d;
}
__device__ __forceinline__ float2 unpk(unsigned long long v) {
    float2 f; asm("mov.b64 {%0, %1}, %2;" : "=f"(f.x), "=f"(f.y) : "l"(v));
    return f;
}

// ---------------------------------------------------------------------------
// Fused, per CTA = (batch b, 16 output rows i0..i0+15), 256 threads,
// ~102 KB smem -> 2 CTAs/SM. Grid = (8, 32) = 256 CTAs.
// ---------------------------------------------------------------------------
__global__ __launch_bounds__(NTHR, 2)
void fused_attn(const float* __restrict__ X, const float* __restrict__ Wd,
                const float* __restrict__ Wk, const float* __restrict__ bl,
                float* __restrict__ out)
{
    extern __shared__ float sm[];
    float* Xs  = sm + OFF_XS;
    float* Wds = sm + OFF_WDS;
    float* As  = sm + OFF_AS;    // logits^T -> normalized alphas [j][t]
    float* Cs  = sm + OFF_CS;
    float* Wks = sm + OFF_WKS;

    const int b   = blockIdx.y;
    const int i0  = blockIdx.x * ITILE;
    const int tid = threadIdx.x;

    const float* Xb = X + b * NT * NF;

    // ---- stage X_b (128x128) and Wd[:128, i0:i0+16] ----
    for (int idx = tid; idx < NT * 32; idx += NTHR) {
        int t = idx >> 5, fv = idx & 31;
        *(float4*)&Xs[t * XS_S + fv * 4] = *(const float4*)&Xb[t * NF + fv * 4];
    }
    for (int idx = tid; idx < NT * 4; idx += NTHR) {
        int k = idx >> 2, jv = idx & 3;
        *(float4*)&Wds[k * WDS_S + jv * 4] = *(const float4*)&Wd[k * NT + i0 + jv * 4];
    }
    __syncthreads();

    // ---- K1: logits, 2t x 4j micro-tile, write transposed into As[j][t] ----
    {
        const int tx = tid & 3;    // j quad: 4*4 = 16
        const int ty = tid >> 2;   // 64 t-row pairs
        unsigned long long acc[2][2] = {};
#pragma unroll 4
        for (int k = 0; k < NF; ++k) {
            unsigned long long xv[2];
#pragma unroll
            for (int a = 0; a < 2; a++) xv[a] = bcast2(Xs[(ty * 2 + a) * XS_S + k]);
            ulonglong2 wp = *(const ulonglong2*)&Wds[k * WDS_S + tx * 4];
#pragma unroll
            for (int a = 0; a < 2; a++) { fma2(acc[a][0], xv[a], wp.x); fma2(acc[a][1], xv[a], wp.y); }
        }
#pragma unroll
        for (int a = 0; a < 2; a++) {
            float2 v0 = unpk(acc[a][0]), v1 = unpk(acc[a][1]);
            const int t = ty * 2 + a;
            As[(tx * 4 + 0) * AS_S + t] = v0.x;
            As[(tx * 4 + 1) * AS_S + t] = v0.y;
            As[(tx * 4 + 2) * AS_S + t] = v1.x;
            As[(tx * 4 + 3) * AS_S + t] = v1.y;
        }
    }
    __syncthreads();

    // ---- softmax over t, in place in As (8 warps x 2 columns) ----
    {
        const int w = tid >> 5, lane = tid & 31;
#pragma unroll
        for (int c = 0; c < 2; ++c) {
            const int jl = w * 2 + c;
            float v[4];
#pragma unroll
            for (int r = 0; r < 4; r++) v[r] = As[jl * AS_S + lane + 32 * r];
            float m = fmaxf(fmaxf(v[0], v[1]), fmaxf(v[2], v[3]));
#pragma unroll
            for (int o = 16; o > 0; o >>= 1) m = fmaxf(m, __shfl_xor_sync(0xffffffffu, m, o));
            float s = 0.0f;
#pragma unroll
            for (int r = 0; r < 4; r++) { v[r] = __expf(v[r] - m); s += v[r]; }
#pragma unroll
            for (int o = 16; o > 0; o >>= 1) s += __shfl_xor_sync(0xffffffffu, s, o);
            const float inv = 1.0f / s;
#pragma unroll
            for (int r = 0; r < 4; r++) As[jl * AS_S + lane + 32 * r] = v[r] * inv;
        }
    }
    __syncthreads();

    // ---- K2: CTX rows, 2i x 4f micro-tile ----
    {
        const int tx = tid & 31;   // f quad: 32*4 = 128
        const int ty = tid >> 5;   // 8 i-row pairs -> 16 rows
        unsigned long long acc[2][2] = {};
#pragma unroll 4
        for (int t = 0; t < NT; ++t) {
            unsigned long long aa[2];
#pragma unroll
            for (int a = 0; a < 2; a++) aa[a] = bcast2(As[(ty * 2 + a) * AS_S + t]);
            ulonglong2 xp = *(const ulonglong2*)&Xs[t * XS_S + tx * 4];
#pragma unroll
            for (int a = 0; a < 2; a++) { fma2(acc[a][0], aa[a], xp.x); fma2(acc[a][1], aa[a], xp.y); }
        }
#pragma unroll
        for (int a = 0; a < 2; a++) {
            ulonglong2 v; v.x = acc[a][0]; v.y = acc[a][1];
            *(ulonglong2*)&Cs[(ty * 2 + a) * CS_S + tx * 4] = v;
        }
    }
    __syncthreads();

    // ---- K3: 3 gates in one pass, Wk streamed in 8-row tiles ----
    {
        const int tx = tid & 31;   // u quad
        const int ty = tid >> 5;   // i row pair
        const int gofs[3] = {0, 256, 384};   // zi, zc, zo
        unsigned long long acc[2][6] = {};

        for (int k0 = 0; k0 < NF; k0 += 8) {
            if (k0) __syncthreads();
            for (int idx = tid; idx < 8 * 96; idx += NTHR) {   // 768 float4
                int k = idx / 96, v = idx % 96;
                int g = v >> 5, uv = v & 31;
                *(float4*)&Wks[k * WKS_S + g * 128 + uv * 4] =
                    *(const float4*)&Wk[(k0 + k) * NG + gofs[g] + uv * 4];
            }
            __syncthreads();
#pragma unroll
            for (int k = 0; k < 8; ++k) {
                unsigned long long cc[2];
#pragma unroll
                for (int a = 0; a < 2; a++) cc[a] = bcast2(Cs[(ty * 2 + a) * CS_S + k0 + k]);
#pragma unroll
                for (int g = 0; g < 3; ++g) {
                    ulonglong2 wp = *(const ulonglong2*)&Wks[k * WKS_S + g * 128 + tx * 4];
#pragma unroll
                    for (int a = 0; a < 2; a++) {
                        fma2(acc[a][2 * g],     cc[a], wp.x);
                        fma2(acc[a][2 * g + 1], cc[a], wp.y);
                    }
                }
            }
        }

        float blv[3][4];
#pragma unroll
        for (int g = 0; g < 3; ++g)
#pragma unroll
            for (int c = 0; c < 4; c++) blv[g][c] = __ldg(&bl[gofs[g] + tx * 4 + c]);

#pragma unroll
        for (int a = 0; a < 2; a++) {
            float z[3][4];
#pragma unroll
            for (int g = 0; g < 3; ++g) {
                float2 v0 = unpk(acc[a][2 * g]), v1 = unpk(acc[a][2 * g + 1]);
                z[g][0] = v0.x + blv[g][0]; z[g][1] = v0.y + blv[g][1];
                z[g][2] = v1.x + blv[g][2]; z[g][3] = v1.y + blv[g][3];
            }
            float h[4];
#pragma unroll
            for (int c = 0; c < 4; c++) {
                float cell = sigf(z[0][c]) * tanhf(z[1][c]);
                h[c] = sigf(z[2][c]) * tanhf(cell);
            }
            float4 v = make_float4(h[0], h[1], h[2], h[3]);
            *(float4*)&out[(b * NT + i0 + ty * 2 + a) * NF + tx * 4] = v;
        }
    }
}

extern "C" void kernel_launch(void* const* d_in, const int* in_sizes, int n_in,
                              void* d_out, int out_size)
{
    const float* X  = (const float*)d_in[0];   // (32,128,128)
    const float* Wd = (const float*)d_in[1];   // (256,128) -- rows [0:128)
    const float* Wk = (const float*)d_in[3];   // (128,512)
    const float* bl = (const float*)d_in[5];   // (512,)
    float* out = (float*)d_out;                // (32,128,128)

    cudaFuncSetAttribute(fused_attn, cudaFuncAttributeMaxDynamicSharedMemorySize, SMEM_BYTES);
    fused_attn<<<dim3(NT / ITILE, NB), NTHR, SMEM_BYTES>>>(X, Wd, Wk, bl, out);
}

// round 8
// speedup vs baseline: 1.6274x; 1.1233x over previous
#include <cuda_runtime.h>
#include <math.h>

#define NB 32
#define NT 128
#define NF 128
#define NG 512

#define ITILE 32
#define NTHR  512

// SMEM strides/offsets (floats)
#define XS_S  132
#define WDS_S 36
#define AS_S  132
#define CS_S  132
#define WKS_S 388

#define OFF_XS  0
#define OFF_WDS (OFF_XS  + NT * XS_S)          // 16896
#define OFF_AS  (OFF_WDS + NT * WDS_S)         // 21504
#define OFF_CS  (OFF_AS  + ITILE * AS_S)       // 25728
#define OFF_WKS (OFF_CS  + ITILE * CS_S)       // 29952
#define SMEM_FLOATS (OFF_WKS + 32 * WKS_S)     // 42368
#define SMEM_BYTES  (SMEM_FLOATS * 4)          // 169472 -> 1 CTA/SM, 16 warps

__device__ __forceinline__ float sigf(float x) { return 1.0f / (1.0f + __expf(-x)); }

__device__ __forceinline__ void fma2(unsigned long long& d,
                                     unsigned long long a, unsigned long long b) {
    asm("fma.rn.f32x2 %0, %1, %2, %0;" : "+l"(d) : "l"(a), "l"(b));
}
__device__ __forceinline__ unsigned long long bcast2(float x) {
    unsigned long long d; unsigned int xi = __float_as_uint(x);
    asm("mov.b64 %0, {%1, %1};" : "=l"(d) : "r"(xi));
    return d;
}
__device__ __forceinline__ float2 unpk(unsigned long long v) {
    float2 f; asm("mov.b64 {%0, %1}, %2;" : "=f"(f.x), "=f"(f.y) : "l"(v));
    return f;
}

// ---------------------------------------------------------------------------
// Fused, per CTA = (batch b, 32 output rows i0..i0+31), 512 threads (16 warps),
// ~165 KB smem -> 1 CTA/SM. Grid = (4, 32) = 128 CTAs.
// Same tile geometry + inner-loop shape as the 31.5us R4 kernel; 2x warps/SMSP.
// ---------------------------------------------------------------------------
__global__ __launch_bounds__(NTHR, 1)
void fused_attn(const float* __restrict__ X, const float* __restrict__ Wd,
                const float* __restrict__ Wk, const float* __restrict__ bl,
                float* __restrict__ out)
{
    extern __shared__ float sm[];
    float* Xs  = sm + OFF_XS;
    float* Wds = sm + OFF_WDS;
    float* As  = sm + OFF_AS;    // logits^T -> normalized alphas [j][t]
    float* Cs  = sm + OFF_CS;
    float* Wks = sm + OFF_WKS;

    const int b   = blockIdx.y;
    const int i0  = blockIdx.x * ITILE;
    const int tid = threadIdx.x;

    const float* Xb = X + b * NT * NF;

    // ---- stage X_b (128x128) and Wd[:128, i0:i0+32] ----
    for (int idx = tid; idx < NT * 32; idx += NTHR) {
        int t = idx >> 5, fv = idx & 31;
        *(float4*)&Xs[t * XS_S + fv * 4] = *(const float4*)&Xb[t * NF + fv * 4];
    }
    for (int idx = tid; idx < NT * 8; idx += NTHR) {
        int k = idx >> 3, jv = idx & 7;
        *(float4*)&Wds[k * WDS_S + jv * 4] = *(const float4*)&Wd[k * NT + i0 + jv * 4];
    }
    __syncthreads();

    // ---- K1: logits, 2t x 4j micro-tile, write transposed into As[j][t] ----
    {
        const int tx = tid & 7;    // j quad: 8*4 = 32
        const int ty = tid >> 3;   // 64 t-row pairs -> 128 rows
        unsigned long long acc[2][2] = {};
#pragma unroll 4
        for (int k = 0; k < NF; ++k) {
            unsigned long long xv[2];
#pragma unroll
            for (int a = 0; a < 2; a++) xv[a] = bcast2(Xs[(ty * 2 + a) * XS_S + k]);
            ulonglong2 wp = *(const ulonglong2*)&Wds[k * WDS_S + tx * 4];
#pragma unroll
            for (int a = 0; a < 2; a++) { fma2(acc[a][0], xv[a], wp.x); fma2(acc[a][1], xv[a], wp.y); }
        }
#pragma unroll
        for (int a = 0; a < 2; a++) {
            float2 v0 = unpk(acc[a][0]), v1 = unpk(acc[a][1]);
            const int t = ty * 2 + a;
            As[(tx * 4 + 0) * AS_S + t] = v0.x;
            As[(tx * 4 + 1) * AS_S + t] = v0.y;
            As[(tx * 4 + 2) * AS_S + t] = v1.x;
            As[(tx * 4 + 3) * AS_S + t] = v1.y;
        }
    }
    __syncthreads();

    // ---- softmax over t, in place in As (16 warps x 2 columns = 32) ----
    {
        const int w = tid >> 5, lane = tid & 31;
#pragma unroll
        for (int c = 0; c < 2; ++c) {
            const int jl = w * 2 + c;
            float v[4];
#pragma unroll
            for (int r = 0; r < 4; r++) v[r] = As[jl * AS_S + lane + 32 * r];
            float m = fmaxf(fmaxf(v[0], v[1]), fmaxf(v[2], v[3]));
#pragma unroll
            for (int o = 16; o > 0; o >>= 1) m = fmaxf(m, __shfl_xor_sync(0xffffffffu, m, o));
            float s = 0.0f;
#pragma unroll
            for (int r = 0; r < 4; r++) { v[r] = __expf(v[r] - m); s += v[r]; }
#pragma unroll
            for (int o = 16; o > 0; o >>= 1) s += __shfl_xor_sync(0xffffffffu, s, o);
            const float inv = 1.0f / s;
#pragma unroll
            for (int r = 0; r < 4; r++) As[jl * AS_S + lane + 32 * r] = v[r] * inv;
        }
    }
    __syncthreads();

    // ---- K2: CTX rows, 2i x 4f micro-tile ----
    {
        const int tx = tid & 31;   // f quad: 32*4 = 128
        const int ty = tid >> 5;   // 16 i-row pairs -> 32 rows
        unsigned long long acc[2][2] = {};
#pragma unroll 4
        for (int t = 0; t < NT; ++t) {
            unsigned long long aa[2];
#pragma unroll
            for (int a = 0; a < 2; a++) aa[a] = bcast2(As[(ty * 2 + a) * AS_S + t]);
            ulonglong2 xp = *(const ulonglong2*)&Xs[t * XS_S + tx * 4];
#pragma unroll
            for (int a = 0; a < 2; a++) { fma2(acc[a][0], aa[a], xp.x); fma2(acc[a][1], aa[a], xp.y); }
        }
#pragma unroll
        for (int a = 0; a < 2; a++) {
            ulonglong2 v; v.x = acc[a][0]; v.y = acc[a][1];
            *(ulonglong2*)&Cs[(ty * 2 + a) * CS_S + tx * 4] = v;
        }
    }
    __syncthreads();

    // ---- K3: 3 gates in one pass, Wk streamed in 32-row tiles (4 iters) ----
    {
        const int tx = tid & 31;   // u quad
        const int ty = tid >> 5;   // i row pair
        const int gofs[3] = {0, 256, 384};   // zi, zc, zo
        unsigned long long acc[2][6] = {};

        for (int k0 = 0; k0 < NF; k0 += 32) {
            if (k0) __syncthreads();
            for (int idx = tid; idx < 32 * 96; idx += NTHR) {   // 3072 float4
                int k = idx / 96, v = idx % 96;
                int g = v >> 5, uv = v & 31;
                *(float4*)&Wks[k * WKS_S + g * 128 + uv * 4] =
                    *(const float4*)&Wk[(k0 + k) * NG + gofs[g] + uv * 4];
            }
            __syncthreads();
#pragma unroll 4
            for (int k = 0; k < 32; ++k) {
                unsigned long long cc[2];
#pragma unroll
                for (int a = 0; a < 2; a++) cc[a] = bcast2(Cs[(ty * 2 + a) * CS_S + k0 + k]);
#pragma unroll
                for (int g = 0; g < 3; ++g) {
                    ulonglong2 wp = *(const ulonglong2*)&Wks[k * WKS_S + g * 128 + tx * 4];
#pragma unroll
                    for (int a = 0; a < 2; a++) {
                        fma2(acc[a][2 * g],     cc[a], wp.x);
                        fma2(acc[a][2 * g + 1], cc[a], wp.y);
                    }
                }
            }
        }

        float blv[3][4];
#pragma unroll
        for (int g = 0; g < 3; ++g)
#pragma unroll
            for (int c = 0; c < 4; c++) blv[g][c] = __ldg(&bl[gofs[g] + tx * 4 + c]);

#pragma unroll
        for (int a = 0; a < 2; a++) {
            float z[3][4];
#pragma unroll
            for (int g = 0; g < 3; ++g) {
                float2 v0 = unpk(acc[a][2 * g]), v1 = unpk(acc[a][2 * g + 1]);
                z[g][0] = v0.x + blv[g][0]; z[g][1] = v0.y + blv[g][1];
                z[g][2] = v1.x + blv[g][2]; z[g][3] = v1.y + blv[g][3];
            }
            float h[4];
#pragma unroll
            for (int c = 0; c < 4; c++) {
                float cell = sigf(z[0][c]) * tanhf(z[1][c]);
                h[c] = sigf(z[2][c]) * tanhf(cell);
            }
            float4 v = make_float4(h[0], h[1], h[2], h[3]);
            *(float4*)&out[(b * NT + i0 + ty * 2 + a) * NF + tx * 4] = v;
        }
    }
}

extern "C" void kernel_launch(void* const* d_in, const int* in_sizes, int n_in,
                              void* d_out, int out_size)
{
    const float* X  = (const float*)d_in[0];   // (32,128,128)
    const float* Wd = (const float*)d_in[1];   // (256,128) -- rows [0:128)
    const float* Wk = (const float*)d_in[3];   // (128,512)
    const float* bl = (const float*)d_in[5];   // (512,)
    float* out = (float*)d_out;                // (32,128,128)

    cudaFuncSetAttribute(fused_attn, cudaFuncAttributeMaxDynamicSharedMemorySize, SMEM_BYTES);
    fused_attn<<<dim3(NT / ITILE, NB), NTHR, SMEM_BYTES>>>(X, Wd, Wk, bl, out);
}

// round 12
// speedup vs baseline: 1.7276x; 1.0616x over previous
#include <cuda_runtime.h>
#include <cuda_bf16.h>
#include <math.h>
#include <stdint.h>

#define NB 32
#define NT 128
#define NF 128

#define SP 136                   // bf16 elements per row (128 + 8 pad -> 4-bank row shift)
#define TILE_HI   (128 * SP * 2) // 34816 bytes: one 128-row hi tile
#define TILE_PAIR (2 * TILE_HI)  // 69632: hi + lo
#define STRIP_HI  (32 * SP * 2)  // 8704: 32-row hi strip
#define STRIP_PAIR (2 * STRIP_HI)

// Prepped bf16 hi/lo operand images (row-major, stride SP, lo tile at +TILE_HI)
__device__ __align__(16) unsigned char g_XA[NB][TILE_PAIR];  // [t][f]
__device__ __align__(16) unsigned char g_XT[NB][TILE_PAIR];  // [f][t]
__device__ __align__(16) unsigned char g_Wd[TILE_PAIR];      // [j][f]  (B layout for G1)
__device__ __align__(16) unsigned char g_Wk[3][TILE_PAIR];   // [u][f]  (B layout, zi/zc/zo)

__device__ __forceinline__ float sigf(float x) { return 1.0f / (1.0f + __expf(-x)); }

// ---------------------------------------------------------------------------
// Prep: f32 inputs -> bf16 hi/lo row-major images (stride SP)
// ---------------------------------------------------------------------------
__global__ void prep_kernel(const float* __restrict__ X, const float* __restrict__ Wd,
                            const float* __restrict__ Wk)
{
    int gid = blockIdx.x * blockDim.x + threadIdx.x;
    const int total = 68 * 2048;   // 68 tiles x 128 rows x 16 chunks (8 cols)
    for (int idx = gid; idx < total; idx += gridDim.x * blockDim.x) {
        int tile = idx >> 11;
        int r, chunk;
        if (tile < 32) { chunk = idx & 15; r = (idx >> 4) & 127; }   // XA: row-major read
        else           { r = idx & 127;   chunk = (idx >> 7) & 15; } // transposed reads: lanes vary r
        int c0 = chunk * 8;
        float v[8];
        unsigned char* dst;
        if (tile < 32) {
            const float* Xb = X + tile * NT * NF;
#pragma unroll
            for (int q = 0; q < 8; q++) v[q] = Xb[r * NF + c0 + q];
            dst = g_XA[tile];
        } else if (tile < 64) {
            const float* Xb = X + (tile - 32) * NT * NF;
#pragma unroll
            for (int q = 0; q < 8; q++) v[q] = Xb[(c0 + q) * NF + r];   // XT[f=r][t=c]
            dst = g_XT[tile - 32];
        } else if (tile == 64) {
#pragma unroll
            for (int q = 0; q < 8; q++) v[q] = Wd[(c0 + q) * NT + r];   // WdB[j=r][f=c]
            dst = g_Wd;
        } else {
            int gt = tile - 65;
            int gof = (gt == 0) ? 0 : (gt == 1 ? 256 : 384);
#pragma unroll
            for (int q = 0; q < 8; q++) v[q] = Wk[(c0 + q) * 512 + gof + r]; // WkB[u=r][f=c]
            dst = g_Wk[gt];
        }
        unsigned short hi[8], lo[8];
#pragma unroll
        for (int q = 0; q < 8; q++) {
            __nv_bfloat16 h = __float2bfloat16(v[q]);
            __nv_bfloat16 l = __float2bfloat16(v[q] - __bfloat162float(h));
            hi[q] = *(unsigned short*)&h;
            lo[q] = *(unsigned short*)&l;
        }
        uint32_t off = (uint32_t)(r * SP + c0) * 2;
        *(uint4*)(dst + off) = *(uint4*)hi;
        *(uint4*)(dst + TILE_HI + off) = *(uint4*)lo;
    }
}

// ---------------------------------------------------------------------------
// mma.sync m16n8k16 bf16 (sm_80+ baseline PTX -> HMMA, no arch-feature gate)
// ---------------------------------------------------------------------------
__device__ __forceinline__ void mma16816(float* d, uint32_t a0, uint32_t a1,
                                         uint32_t a2, uint32_t a3,
                                         uint32_t b0, uint32_t b1) {
    asm volatile(
        "mma.sync.aligned.m16n8k16.row.col.f32.bf16.bf16.f32 "
        "{%0,%1,%2,%3}, {%4,%5,%6,%7}, {%8,%9}, {%0,%1,%2,%3};"
        : "+f"(d[0]), "+f"(d[1]), "+f"(d[2]), "+f"(d[3])
        : "r"(a0), "r"(a1), "r"(a2), "r"(a3), "r"(b0), "r"(b1));
}
__device__ __forceinline__ uint32_t lds32(const __nv_bfloat16* p) {
    return *(const uint32_t*)p;
}

// SMEM layout (bytes)
#define SM_XA  0
#define SM_XT  TILE_PAIR                 // also reused for Wk gate tiles in G3
#define SM_WD  (2 * TILE_PAIR)           // 139264
#define SM_P   (SM_WD + STRIP_PAIR)      // 156672
#define SM_CTX (SM_P + STRIP_PAIR)       // 174080 (Sbuf f32 aliases here pre-G2)
#define SMEM_TOTAL (SM_CTX + STRIP_PAIR) // 191488

__device__ __forceinline__ void cp16(unsigned char* dst, const unsigned char* src,
                                     int bytes, int tid, int nthr) {
    const uint4* s = (const uint4*)src;
    uint4* d = (uint4*)dst;
    int n = bytes >> 4;
    for (int i = tid; i < n; i += nthr) d[i] = s[i];
}

// one 3-term (hh, hl, lh) K=128 GEMM pass: A strip row arow.., B rows brow0..,
// 4 n-tiles, accumulate into acc[4][4]
__device__ __forceinline__ void gemm3(float acc[4][4],
                                      const __nv_bfloat16* Ah, const __nv_bfloat16* Al,
                                      const __nv_bfloat16* Bh, const __nv_bfloat16* Bl,
                                      int arow, int brow0, int g, int tq) {
#pragma unroll
    for (int term = 0; term < 3; term++) {
        const __nv_bfloat16* A = (term == 2) ? Al : Ah;
        const __nv_bfloat16* B = (term == 1) ? Bl : Bh;
        const __nv_bfloat16* ar0 = A + (arow + g) * SP + 2 * tq;
        const __nv_bfloat16* ar1 = ar0 + 8 * SP;
#pragma unroll
        for (int k0 = 0; k0 < 128; k0 += 16) {
            uint32_t a0 = lds32(ar0 + k0), a1 = lds32(ar1 + k0);
            uint32_t a2 = lds32(ar0 + k0 + 8), a3 = lds32(ar1 + k0 + 8);
#pragma unroll
            for (int nt = 0; nt < 4; nt++) {
                const __nv_bfloat16* br = B + (brow0 + nt * 8 + g) * SP + 2 * tq + k0;
                mma16816(acc[nt], a0, a1, a2, a3, lds32(br), lds32(br + 8));
            }
        }
    }
}

// ---------------------------------------------------------------------------
// Main fused kernel: CTA = (batch b, 32 output rows i0..), 256 threads / 8 warps
// ---------------------------------------------------------------------------
__global__ __launch_bounds__(256, 1)
void main_kernel(const float* __restrict__ bl, float* __restrict__ out)
{
    extern __shared__ unsigned char smem[];
    const int tid = threadIdx.x;
    const int w = tid >> 5, lane = tid & 31, g = lane >> 2, tq = lane & 3;
    const int b = blockIdx.y, i0 = blockIdx.x * 32;

    // stage XA, XT (full pairs), Wd rows i0..i0+31 (hi + lo strips)
    cp16(smem + SM_XA, g_XA[b], TILE_PAIR, tid, 256);
    cp16(smem + SM_XT, g_XT[b], TILE_PAIR, tid, 256);
    cp16(smem + SM_WD, g_Wd + i0 * (SP * 2), STRIP_HI, tid, 256);
    cp16(smem + SM_WD + STRIP_HI, g_Wd + TILE_HI + i0 * (SP * 2), STRIP_HI, tid, 256);
    __syncthreads();

    const __nv_bfloat16* XAh = (const __nv_bfloat16*)(smem + SM_XA);
    const __nv_bfloat16* XAl = (const __nv_bfloat16*)(smem + SM_XA + TILE_HI);
    const __nv_bfloat16* XTh = (const __nv_bfloat16*)(smem + SM_XT);
    const __nv_bfloat16* XTl = (const __nv_bfloat16*)(smem + SM_XT + TILE_HI);
    const __nv_bfloat16* WDh = (const __nv_bfloat16*)(smem + SM_WD);
    const __nv_bfloat16* WDl = (const __nv_bfloat16*)(smem + SM_WD + STRIP_HI);
    __nv_bfloat16* Ph = (__nv_bfloat16*)(smem + SM_P);
    __nv_bfloat16* Pl = (__nv_bfloat16*)(smem + SM_P + STRIP_HI);
    __nv_bfloat16* Ch = (__nv_bfloat16*)(smem + SM_CTX);
    __nv_bfloat16* Cl = (__nv_bfloat16*)(smem + SM_CTX + STRIP_HI);
    float* Sbuf = (float*)(smem + SM_CTX);   // aliases CTX region; dead after softmax

    // ---- G1: S[t][j] = X @ WdB^T.  warp w: t-strip 16w, all 32 j ----
    {
        float acc[4][4] = {};
        gemm3(acc, XAh, XAl, WDh, WDl, w * 16, 0, g, tq);
        const int r0 = w * 16 + g;
#pragma unroll
        for (int nt = 0; nt < 4; nt++) {
            int c = nt * 8 + 2 * tq;
            Sbuf[r0 * 33 + c]     = acc[nt][0];
            Sbuf[r0 * 33 + c + 1] = acc[nt][1];
            Sbuf[(r0 + 8) * 33 + c]     = acc[nt][2];
            Sbuf[(r0 + 8) * 33 + c + 1] = acc[nt][3];
        }
    }
    __syncthreads();

    // ---- softmax over t per column j; P[j][t] bf16 hi/lo ----
    {
#pragma unroll
        for (int c = 0; c < 4; c++) {
            const int j = w * 4 + c;
            float v[4];
#pragma unroll
            for (int r = 0; r < 4; r++) v[r] = Sbuf[(lane + 32 * r) * 33 + j];
            float m = fmaxf(fmaxf(v[0], v[1]), fmaxf(v[2], v[3]));
#pragma unroll
            for (int o = 16; o > 0; o >>= 1) m = fmaxf(m, __shfl_xor_sync(0xffffffffu, m, o));
            float s = 0.f;
#pragma unroll
            for (int r = 0; r < 4; r++) { v[r] = __expf(v[r] - m); s += v[r]; }
#pragma unroll
            for (int o = 16; o > 0; o >>= 1) s += __shfl_xor_sync(0xffffffffu, s, o);
            const float inv = 1.0f / s;
#pragma unroll
            for (int r = 0; r < 4; r++) {
                float a = v[r] * inv;
                __nv_bfloat16 h = __float2bfloat16(a);
                __nv_bfloat16 l = __float2bfloat16(a - __bfloat162float(h));
                Ph[j * SP + lane + 32 * r] = h;
                Pl[j * SP + lane + 32 * r] = l;
            }
        }
    }
    __syncthreads();

    // ---- G2: CTX[i][f] = P @ XT^T.  warp w: m-strip (w&1)*16, n-range (w>>1)*32 ----
    const int mw = (w & 1) * 16;
    const int n0 = (w >> 1) * 32;
    {
        float acc[4][4] = {};
        gemm3(acc, Ph, Pl, XTh, XTl, mw, n0, g, tq);
        const int r0 = mw + g;
#pragma unroll
        for (int nt = 0; nt < 4; nt++) {
            int c = n0 + nt * 8 + 2 * tq;
#pragma unroll
            for (int q = 0; q < 4; q++) {
                int rr = (q < 2) ? r0 : r0 + 8;
                int cc = c + (q & 1);
                float x = acc[nt][q];
                __nv_bfloat16 h = __float2bfloat16(x);
                __nv_bfloat16 l = __float2bfloat16(x - __bfloat162float(h));
                Ch[rr * SP + cc] = h;
                Cl[rr * SP + cc] = l;
            }
        }
    }

    // ---- G3: three gates, Wk gate tiles streamed into the XT region ----
    float aI[4][4] = {}, aC[4][4] = {}, aO[4][4] = {};
#pragma unroll
    for (int gate = 0; gate < 3; gate++) {
        __syncthreads();   // prior reads of XT region done; CTX visible (first iter)
        cp16(smem + SM_XT, g_Wk[gate], TILE_PAIR, tid, 256);
        __syncthreads();
        float (*acc)[4] = (gate == 0) ? aI : (gate == 1) ? aC : aO;
        gemm3(acc, Ch, Cl, XTh, XTl, mw, n0, g, tq);
    }

    // ---- epilogue: bias + LSTM cell, write out ----
    {
        const int r0 = i0 + mw + g;
#pragma unroll
        for (int nt = 0; nt < 4; nt++) {
            int u0 = n0 + nt * 8 + 2 * tq;
#pragma unroll
            for (int q = 0; q < 4; q++) {
                int rr = (q < 2) ? r0 : r0 + 8;
                int u = u0 + (q & 1);
                float zi = aI[nt][q] + __ldg(&bl[u]);
                float zc = aC[nt][q] + __ldg(&bl[256 + u]);
                float zo = aO[nt][q] + __ldg(&bl[384 + u]);
                float cell = sigf(zi) * tanhf(zc);
                out[(b * NT + rr) * NF + u] = sigf(zo) * tanhf(cell);
            }
        }
    }
}

extern "C" void kernel_launch(void* const* d_in, const int* in_sizes, int n_in,
                              void* d_out, int out_size)
{
    const float* X  = (const float*)d_in[0];   // (32,128,128)
    const float* Wd = (const float*)d_in[1];   // (256,128), rows [0:128) used
    const float* Wk = (const float*)d_in[3];   // (128,512)
    const float* bl = (const float*)d_in[5];   // (512,)
    float* out = (float*)d_out;                // (32,128,128)

    prep_kernel<<<272, 256>>>(X, Wd, Wk);
    cudaFuncSetAttribute(main_kernel, cudaFuncAttributeMaxDynamicSharedMemorySize, SMEM_TOTAL);
    main_kernel<<<dim3(4, NB), 256, SMEM_TOTAL>>>(bl, out);
}

// round 13
// speedup vs baseline: 2.9817x; 1.7259x over previous
#include <cuda_runtime.h>
#include <cuda_bf16.h>
#include <math.h>
#include <stdint.h>

#define NB 32
#define NT 128
#define NF 128

#define SP 136                   // bf16 per row (128 + 8 pad)
#define TILE_HI   (128 * SP * 2) // 34816 B
#define TILE_PAIR (2 * TILE_HI)  // 69632 B
#define STRIP_HI  (32 * SP * 2)  // 8704 B
#define STRIP_PAIR (2 * STRIP_HI)

#define NTHR 512

__device__ __align__(16) unsigned char g_XA[NB][TILE_PAIR];  // [t][f]
__device__ __align__(16) unsigned char g_XT[NB][TILE_PAIR];  // [f][t]
__device__ __align__(16) unsigned char g_Wd[TILE_PAIR];      // [j][f]
__device__ __align__(16) unsigned char g_Wk[3][TILE_PAIR];   // [u][f] zi/zc/zo

__device__ __forceinline__ float sigf(float x) { return 1.0f / (1.0f + __expf(-x)); }

// ---------------------------------------------------------------------------
// Prep: f32 -> bf16 hi/lo images
// ---------------------------------------------------------------------------
__global__ void prep_kernel(const float* __restrict__ X, const float* __restrict__ Wd,
                            const float* __restrict__ Wk)
{
    int gid = blockIdx.x * blockDim.x + threadIdx.x;
    const int total = 68 * 2048;
    for (int idx = gid; idx < total; idx += gridDim.x * blockDim.x) {
        int tile = idx >> 11;
        int r, chunk;
        if (tile < 32) { chunk = idx & 15; r = (idx >> 4) & 127; }
        else           { r = idx & 127;   chunk = (idx >> 7) & 15; }
        int c0 = chunk * 8;
        float v[8];
        unsigned char* dst;
        if (tile < 32) {
            const float* Xb = X + tile * NT * NF;
#pragma unroll
            for (int q = 0; q < 8; q++) v[q] = Xb[r * NF + c0 + q];
            dst = g_XA[tile];
        } else if (tile < 64) {
            const float* Xb = X + (tile - 32) * NT * NF;
#pragma unroll
            for (int q = 0; q < 8; q++) v[q] = Xb[(c0 + q) * NF + r];
            dst = g_XT[tile - 32];
        } else if (tile == 64) {
#pragma unroll
            for (int q = 0; q < 8; q++) v[q] = Wd[(c0 + q) * NT + r];
            dst = g_Wd;
        } else {
            int gt = tile - 65;
            int gof = (gt == 0) ? 0 : (gt == 1 ? 256 : 384);
#pragma unroll
            for (int q = 0; q < 8; q++) v[q] = Wk[(c0 + q) * 512 + gof + r];
            dst = g_Wk[gt];
        }
        unsigned short hi[8], lo[8];
#pragma unroll
        for (int q = 0; q < 8; q++) {
            __nv_bfloat16 h = __float2bfloat16(v[q]);
            __nv_bfloat16 l = __float2bfloat16(v[q] - __bfloat162float(h));
            hi[q] = *(unsigned short*)&h;
            lo[q] = *(unsigned short*)&l;
        }
        uint32_t off = (uint32_t)(r * SP + c0) * 2;
        *(uint4*)(dst + off) = *(uint4*)hi;
        *(uint4*)(dst + TILE_HI + off) = *(uint4*)lo;
    }
}

// ---------------------------------------------------------------------------
// mma.sync m16n8k16 bf16 + cp.async (both sm_80 baseline PTX)
// ---------------------------------------------------------------------------
__device__ __forceinline__ void mma16816(float* d, uint32_t a0, uint32_t a1,
                                         uint32_t a2, uint32_t a3,
                                         uint32_t b0, uint32_t b1) {
    asm volatile(
        "mma.sync.aligned.m16n8k16.row.col.f32.bf16.bf16.f32 "
        "{%0,%1,%2,%3}, {%4,%5,%6,%7}, {%8,%9}, {%0,%1,%2,%3};"
        : "+f"(d[0]), "+f"(d[1]), "+f"(d[2]), "+f"(d[3])
        : "r"(a0), "r"(a1), "r"(a2), "r"(a3), "r"(b0), "r"(b1));
}
__device__ __forceinline__ uint32_t lds32(const __nv_bfloat16* p) {
    return *(const uint32_t*)p;
}
__device__ __forceinline__ void cpa16(unsigned char* dst, const unsigned char* src) {
    uint32_t d = (uint32_t)__cvta_generic_to_shared(dst);
    asm volatile("cp.async.cg.shared.global [%0], [%1], 16;" :: "r"(d), "l"(src));
}
#define CPA_COMMIT() asm volatile("cp.async.commit_group;" ::: "memory")
#define CPA_WAIT(n)  asm volatile("cp.async.wait_group %0;" :: "n"(n) : "memory")

__device__ __forceinline__ void cpa_tile(unsigned char* dst, const unsigned char* src,
                                         int bytes, int tid) {
    for (int i = tid * 16; i < bytes; i += NTHR * 16) cpa16(dst + i, src + i);
}

// SMEM layout (bytes)
#define SM_XA  0                          // XA pair -> Wk0 -> Wk2
#define SM_XT  TILE_PAIR                  // XT pair -> Wk1
#define SM_WD  (2 * TILE_PAIR)            // 139264
#define SM_P   (SM_WD + STRIP_PAIR)       // 156672
#define SM_CTX (SM_P + STRIP_PAIR)        // 174080 (Sbuf f32 aliases)
#define SMEM_TOTAL (SM_CTX + STRIP_PAIR)  // 191488

// one 3-term K=128 pass, 2 n-tiles
__device__ __forceinline__ void gemm3(float acc[2][4],
                                      const __nv_bfloat16* Ah, const __nv_bfloat16* Al,
                                      const __nv_bfloat16* Bh, const __nv_bfloat16* Bl,
                                      int arow, int brow0, int g, int tq) {
#pragma unroll
    for (int term = 0; term < 3; term++) {
        const __nv_bfloat16* A = (term == 2) ? Al : Ah;
        const __nv_bfloat16* B = (term == 1) ? Bl : Bh;
        const __nv_bfloat16* ar0 = A + (arow + g) * SP + 2 * tq;
        const __nv_bfloat16* ar1 = ar0 + 8 * SP;
#pragma unroll
        for (int k0 = 0; k0 < 128; k0 += 16) {
            uint32_t a0 = lds32(ar0 + k0), a1 = lds32(ar1 + k0);
            uint32_t a2 = lds32(ar0 + k0 + 8), a3 = lds32(ar1 + k0 + 8);
#pragma unroll
            for (int nt = 0; nt < 2; nt++) {
                const __nv_bfloat16* br = B + (brow0 + nt * 8 + g) * SP + 2 * tq + k0;
                mma16816(acc[nt], a0, a1, a2, a3, lds32(br), lds32(br + 8));
            }
        }
    }
}

// ---------------------------------------------------------------------------
// Main: CTA = (batch b, 32 rows i0..), 512 threads / 16 warps
// ---------------------------------------------------------------------------
__global__ __launch_bounds__(NTHR, 1)
void main_kernel(const float* __restrict__ bl, float* __restrict__ out)
{
    extern __shared__ unsigned char smem[];
    const int tid = threadIdx.x;
    const int w = tid >> 5, lane = tid & 31, g = lane >> 2, tq = lane & 3;
    const int b = blockIdx.y, i0 = blockIdx.x * 32;

    // initial stage via cp.async: XA, XT, Wd strips
    cpa_tile(smem + SM_XA, g_XA[b], TILE_PAIR, tid);
    cpa_tile(smem + SM_XT, g_XT[b], TILE_PAIR, tid);
    cpa_tile(smem + SM_WD, g_Wd + i0 * (SP * 2), STRIP_HI, tid);
    cpa_tile(smem + SM_WD + STRIP_HI, g_Wd + TILE_HI + i0 * (SP * 2), STRIP_HI, tid);
    CPA_COMMIT();
    CPA_WAIT(0);
    __syncthreads();

    const __nv_bfloat16* XAh = (const __nv_bfloat16*)(smem + SM_XA);
    const __nv_bfloat16* XAl = (const __nv_bfloat16*)(smem + SM_XA + TILE_HI);
    const __nv_bfloat16* XTh = (const __nv_bfloat16*)(smem + SM_XT);
    const __nv_bfloat16* XTl = (const __nv_bfloat16*)(smem + SM_XT + TILE_HI);
    const __nv_bfloat16* WDh = (const __nv_bfloat16*)(smem + SM_WD);
    const __nv_bfloat16* WDl = (const __nv_bfloat16*)(smem + SM_WD + STRIP_HI);
    __nv_bfloat16* Ph = (__nv_bfloat16*)(smem + SM_P);
    __nv_bfloat16* Pl = (__nv_bfloat16*)(smem + SM_P + STRIP_HI);
    __nv_bfloat16* Ch = (__nv_bfloat16*)(smem + SM_CTX);
    __nv_bfloat16* Cl = (__nv_bfloat16*)(smem + SM_CTX + STRIP_HI);
    float* Sbuf = (float*)(smem + SM_CTX);   // aliases CTX; dead after softmax

    // ---- G1: S[t][j]. warp w: t-strip (w&7)*16, j-half (w>>3)*16 ----
    {
        float acc[2][4] = {};
        const int t0 = (w & 7) * 16, jh = (w >> 3) * 16;
        gemm3(acc, XAh, XAl, WDh, WDl, t0, jh, g, tq);
        const int r0 = t0 + g;
#pragma unroll
        for (int nt = 0; nt < 2; nt++) {
            int c = jh + nt * 8 + 2 * tq;
            Sbuf[r0 * 33 + c]     = acc[nt][0];
            Sbuf[r0 * 33 + c + 1] = acc[nt][1];
            Sbuf[(r0 + 8) * 33 + c]     = acc[nt][2];
            Sbuf[(r0 + 8) * 33 + c + 1] = acc[nt][3];
        }
    }
    __syncthreads();   // XA reads done; Sbuf visible

    // prefetch Wk0 into the (dead) XA region; overlaps softmax + G2
    cpa_tile(smem + SM_XA, g_Wk[0], TILE_PAIR, tid);
    CPA_COMMIT();

    // ---- softmax over t per column j (16 warps x 2 cols); P[j][t] hi/lo ----
    {
#pragma unroll
        for (int c = 0; c < 2; c++) {
            const int j = w * 2 + c;
            float v[4];
#pragma unroll
            for (int r = 0; r < 4; r++) v[r] = Sbuf[(lane + 32 * r) * 33 + j];
            float m = fmaxf(fmaxf(v[0], v[1]), fmaxf(v[2], v[3]));
#pragma unroll
            for (int o = 16; o > 0; o >>= 1) m = fmaxf(m, __shfl_xor_sync(0xffffffffu, m, o));
            float s = 0.f;
#pragma unroll
            for (int r = 0; r < 4; r++) { v[r] = __expf(v[r] - m); s += v[r]; }
#pragma unroll
            for (int o = 16; o > 0; o >>= 1) s += __shfl_xor_sync(0xffffffffu, s, o);
            const float inv = 1.0f / s;
#pragma unroll
            for (int r = 0; r < 4; r++) {
                float a = v[r] * inv;
                __nv_bfloat16 h = __float2bfloat16(a);
                __nv_bfloat16 l = __float2bfloat16(a - __bfloat162float(h));
                Ph[j * SP + lane + 32 * r] = h;
                Pl[j * SP + lane + 32 * r] = l;
            }
        }
    }
    __syncthreads();   // Sbuf reads done (CTX region reusable); P visible

    // ---- G2: CTX[i][f]. warp w: m-strip (w&1)*16, n0 (w>>1)*16 ----
    const int mw = (w & 1) * 16;
    const int n0 = (w >> 1) * 16;
    {
        float acc[2][4] = {};
        gemm3(acc, Ph, Pl, XTh, XTl, mw, n0, g, tq);
        const int r0 = mw + g;
#pragma unroll
        for (int nt = 0; nt < 2; nt++) {
            int c = n0 + nt * 8 + 2 * tq;
#pragma unroll
            for (int q = 0; q < 4; q++) {
                int rr = (q < 2) ? r0 : r0 + 8;
                int cc = c + (q & 1);
                float x = acc[nt][q];
                __nv_bfloat16 h = __float2bfloat16(x);
                __nv_bfloat16 l = __float2bfloat16(x - __bfloat162float(h));
                Ch[rr * SP + cc] = h;
                Cl[rr * SP + cc] = l;
            }
        }
    }
    __syncthreads();   // XT reads done; CTX visible

    // prefetch Wk1 into the (dead) XT region; overlaps gate0
    cpa_tile(smem + SM_XT, g_Wk[1], TILE_PAIR, tid);
    CPA_COMMIT();

    // wait for Wk0 (allow Wk1 in flight), then gate0 from XA region
    CPA_WAIT(1);
    __syncthreads();
    float aI[2][4] = {}, aC[2][4] = {}, aO[2][4] = {};
    gemm3(aI, Ch, Cl, XAh, XAl, mw, n0, g, tq);
    __syncthreads();   // XA (Wk0) reads done

    // prefetch Wk2 into XA region; overlaps gate1
    cpa_tile(smem + SM_XA, g_Wk[2], TILE_PAIR, tid);
    CPA_COMMIT();

    CPA_WAIT(1);       // Wk1 resident
    __syncthreads();
    gemm3(aC, Ch, Cl, XTh, XTl, mw, n0, g, tq);

    CPA_WAIT(0);       // Wk2 resident
    __syncthreads();
    gemm3(aO, Ch, Cl, XAh, XAl, mw, n0, g, tq);

    // ---- epilogue: bias + LSTM cell ----
    {
        const int r0 = i0 + mw + g;
#pragma unroll
        for (int nt = 0; nt < 2; nt++) {
            int u0 = n0 + nt * 8 + 2 * tq;
#pragma unroll
            for (int q = 0; q < 4; q++) {
                int rr = (q < 2) ? r0 : r0 + 8;
                int u = u0 + (q & 1);
                float zi = aI[nt][q] + __ldg(&bl[u]);
                float zc = aC[nt][q] + __ldg(&bl[256 + u]);
                float zo = aO[nt][q] + __ldg(&bl[384 + u]);
                float cell = sigf(zi) * tanhf(zc);
                out[(b * NT + rr) * NF + u] = sigf(zo) * tanhf(cell);
            }
        }
    }
}

extern "C" void kernel_launch(void* const* d_in, const int* in_sizes, int n_in,
                              void* d_out, int out_size)
{
    const float* X  = (const float*)d_in[0];   // (32,128,128)
    const float* Wd = (const float*)d_in[1];   // (256,128), rows [0:128)
    const float* Wk = (const float*)d_in[3];   // (128,512)
    const float* bl = (const float*)d_in[5];   // (512,)
    float* out = (float*)d_out;                // (32,128,128)

    prep_kernel<<<272, 256>>>(X, Wd, Wk);
    cudaFuncSetAttribute(main_kernel, cudaFuncAttributeMaxDynamicSharedMemorySize, SMEM_TOTAL);
    main_kernel<<<dim3(4, NB), NTHR, SMEM_TOTAL>>>(bl, out);
}